// round 4
// baseline (speedup 1.0000x reference)
#include <cuda_runtime.h>
#include <cuda_bf16.h>
#include <cstdint>

#define NROWS 32768
#define KCODES 8192
#define DD 256
#define QSIZE (NROWS * DD)

#define TM 128
#define TN 128
#define NBTILES (KCODES / TN)     // 64
#define NUNITS (NROWS / TM)       // 256
#define CAP 48
#define DELTA 1.2e-3f

// dynamic smem byte offsets
#define SM_A   0
#define SM_B0  65536
#define SM_B1  131072
#define SM_EES 196608
#define SM_ZZ  197120
#define SM_BD  197632
#define SM_TOTAL 198400

// ---- device scratch ----
__device__ int   g_bestk[NROWS];
__device__ float g_zz[NROWS];
__device__ float g_ee[KCODES];
__device__ float g_partial[8192];
__device__ int   g_work;
__device__ int   g_ncand[NROWS];
__device__ int   g_cand[NROWS * CAP];
__device__ __nv_bfloat16 g_cbh[KCODES * DD];

__device__ __forceinline__ uint32_t smem_u32(const void* p) {
    uint32_t a;
    asm("{ .reg .u64 t; cvta.to.shared.u64 t, %1; cvt.u32.u64 %0, t; }" : "=r"(a) : "l"(p));
    return a;
}
#define LDSM4(r0, r1, r2, r3, a) \
    asm volatile("ldmatrix.sync.aligned.m8n8.x4.shared.b16 {%0,%1,%2,%3}, [%4];" \
        : "=r"(r0), "=r"(r1), "=r"(r2), "=r"(r3) : "r"(a))
#define MMA16816(c0, c1, c2, c3, a0, a1, a2, a3, b0, b1) \
    asm volatile("mma.sync.aligned.m16n8k16.row.col.f32.bf16.bf16.f32 " \
        "{%0,%1,%2,%3}, {%4,%5,%6,%7}, {%8,%9}, {%0,%1,%2,%3};" \
        : "+f"(c0), "+f"(c1), "+f"(c2), "+f"(c3) \
        : "r"(a0), "r"(a1), "r"(a2), "r"(a3), "r"(b0), "r"(b1))
#define CPASYNC16(dst, src) \
    asm volatile("cp.async.cg.shared.global [%0], [%1], 16;" :: "r"(dst), "l"(src))
#define CPCOMMIT() asm volatile("cp.async.commit_group;" ::: "memory")
#define CPWAIT1()  asm volatile("cp.async.wait_group 1;" ::: "memory")

// -------- init (graph-replayable) --------
__global__ void vq_init_kernel() {
    int i = blockIdx.x * 256 + threadIdx.x;
    g_ncand[i] = 0;
    if (i == 0) g_work = 0;
}

// -------- exact row squared-norms (matched reference; unchanged) --------
__global__ void vq_norms_kernel(const float* __restrict__ src, float* __restrict__ dst,
                                int nrows) {
    int w = (blockIdx.x * blockDim.x + threadIdx.x) >> 5;
    int lane = threadIdx.x & 31;
    if (w >= nrows) return;
    const float* row = src + (size_t)w * DD;
    float s = 0.f;
#pragma unroll
    for (int j = 0; j < DD / 32; j++) {
        float v = row[lane + 32 * j];
        s = fmaf(v, v, s);
    }
#pragma unroll
    for (int o = 16; o; o >>= 1) s += __shfl_xor_sync(0xffffffffu, s, o);
    if (lane == 0) dst[w] = s;
}

// -------- codebook fp32 -> bf16 --------
__global__ void vq_cvt_kernel(const float* __restrict__ cb) {
    int i = blockIdx.x * 256 + threadIdx.x;
    float4 v = reinterpret_cast<const float4*>(cb)[i];
    __nv_bfloat162 p0 = __floats2bfloat162_rn(v.x, v.y);
    __nv_bfloat162 p1 = __floats2bfloat162_rn(v.z, v.w);
    uint2 w;
    w.x = *reinterpret_cast<uint32_t*>(&p0);
    w.y = *reinterpret_cast<uint32_t*>(&p1);
    reinterpret_cast<uint2*>(g_cbh)[i] = w;
}

// -------- bf16 HMMA screening: approx d, running-min candidate collection --------
// 256 thr = 8 warps (2 M x 4 N). Block tile 128x128, warp tile 64x32, K=256.
// Swizzled bf16 smem: elem (r, k) at r*512 + ((k*2) ^ ((r&7)<<4)).
__global__ void __launch_bounds__(256, 1) vq_screen_kernel(const float* __restrict__ z) {
    extern __shared__ char smem[];
    __shared__ int s_u;
    const uint32_t sbase = smem_u32(smem);
    float* ees = reinterpret_cast<float*>(smem + SM_EES);
    float* zzs = reinterpret_cast<float*>(smem + SM_ZZ);
    unsigned int* bdU = reinterpret_cast<unsigned int*>(smem + SM_BD);

    const int tid = threadIdx.x;
    const int lane = tid & 31;
    const int wid = tid >> 5;
    const int wm = wid & 1;
    const int wn = wid >> 1;
    const int g = lane >> 2;
    const int q = lane & 3;
    const uint32_t swz = (uint32_t)((lane & 7) << 4);
    const uint32_t kb = (uint32_t)((lane >> 4) << 4);

    // ldmatrix base addresses (A fixed; B per buffer)
    uint32_t preA[4], preB[2][2];
#pragma unroll
    for (int i = 0; i < 4; i++)
        preA[i] = sbase + SM_A + (uint32_t)(wm * 64 + i * 16 + (lane & 15)) * 512;
#pragma unroll
    for (int jj = 0; jj < 2; jj++) {
        uint32_t r = (uint32_t)(wn * 32 + jj * 16 + (lane & 15)) * 512;
        preB[0][jj] = sbase + SM_B0 + r;
        preB[1][jj] = sbase + SM_B1 + r;
    }

    // B cp.async loader indices: f = tid + 256*it -> n = f>>5, kc = f&31
    const int ldn = tid >> 5;          // + 8*it
    const int ldkc = tid & 31;

    for (;;) {
        if (tid == 0) s_u = atomicAdd(&g_work, 1);
        __syncthreads();
        const int u = s_u;
        if (u >= NUNITS) return;
        const int row0 = u * TM;

        // ---- A tile: fp32 -> bf16, swizzled ----
        {
            const float4* zg = reinterpret_cast<const float4*>(z) + (size_t)row0 * 64;
#pragma unroll
            for (int it = 0; it < 16; it++) {
                int f = tid + 256 * it;
                int m = f >> 5, kc = f & 31;
                float4 v0 = zg[m * 64 + kc * 2];
                float4 v1 = zg[m * 64 + kc * 2 + 1];
                __nv_bfloat162 p0 = __floats2bfloat162_rn(v0.x, v0.y);
                __nv_bfloat162 p1 = __floats2bfloat162_rn(v0.z, v0.w);
                __nv_bfloat162 p2 = __floats2bfloat162_rn(v1.x, v1.y);
                __nv_bfloat162 p3 = __floats2bfloat162_rn(v1.z, v1.w);
                uint4 w;
                w.x = *reinterpret_cast<uint32_t*>(&p0);
                w.y = *reinterpret_cast<uint32_t*>(&p1);
                w.z = *reinterpret_cast<uint32_t*>(&p2);
                w.w = *reinterpret_cast<uint32_t*>(&p3);
                uint32_t off = (uint32_t)m * 512 + (((uint32_t)kc * 16) ^ ((uint32_t)(m & 7) << 4));
                *reinterpret_cast<uint4*>(smem + SM_A + off) = w;
            }
        }
        if (tid < 128) {
            zzs[tid] = g_zz[row0 + tid];
            bdU[tid] = 0x7f800000u;
        }

        // ---- cp.async B tile 0 -> buf0 ----
#pragma unroll
        for (int it = 0; it < 16; it++) {
            int n = ldn + 8 * it;
            uint32_t dst = sbase + SM_B0 + (uint32_t)n * 512 +
                           (((uint32_t)ldkc * 16) ^ ((uint32_t)(n & 7) << 4));
            const __nv_bfloat16* src = g_cbh + (size_t)n * 256 + ldkc * 8;
            CPASYNC16(dst, src);
        }
        CPCOMMIT();

        for (int t = 0; t < NBTILES; t++) {
            // (previous iter's pass2 finished behind the trailing barrier)
            if (tid < 128) ees[tid] = g_ee[t * 128 + tid];
            // issue next B tile
            if (t + 1 < NBTILES) {
                const int buf1 = (t + 1) & 1;
#pragma unroll
                for (int it = 0; it < 16; it++) {
                    int n = ldn + 8 * it;
                    uint32_t dst = sbase + (buf1 ? SM_B1 : SM_B0) + (uint32_t)n * 512 +
                                   (((uint32_t)ldkc * 16) ^ ((uint32_t)(n & 7) << 4));
                    const __nv_bfloat16* src =
                        g_cbh + (size_t)(t + 1) * TN * 256 + (size_t)n * 256 + ldkc * 8;
                    CPASYNC16(dst, src);
                }
            }
            CPCOMMIT();
            CPWAIT1();           // tile t resident
            __syncthreads();     // visible to all warps; ees/zz/A ready

            // ---- MMA: c[4][4][4] over K=256 ----
            float c[4][4][4];
#pragma unroll
            for (int i = 0; i < 4; i++)
#pragma unroll
                for (int j = 0; j < 4; j++)
#pragma unroll
                    for (int e = 0; e < 4; e++) c[i][j][e] = 0.f;

            const int b = t & 1;
#pragma unroll
            for (int kk = 0; kk < 16; kk++) {
                const uint32_t ko = (((uint32_t)kk << 5) + kb) ^ swz;
                uint32_t a0[4], a1[4], a2[4], a3[4];
#pragma unroll
                for (int i = 0; i < 4; i++)
                    LDSM4(a0[i], a1[i], a2[i], a3[i], preA[i] + ko);
                uint32_t blo[4], bhi[4];
#pragma unroll
                for (int jj = 0; jj < 2; jj++) {
                    uint32_t r0, r1, r2, r3;
                    LDSM4(r0, r1, r2, r3, preB[b][jj] + ko);
                    blo[2 * jj] = r0; blo[2 * jj + 1] = r1;
                    bhi[2 * jj] = r2; bhi[2 * jj + 1] = r3;
                }
#pragma unroll
                for (int i = 0; i < 4; i++)
#pragma unroll
                    for (int j = 0; j < 4; j++)
                        MMA16816(c[i][j][0], c[i][j][1], c[i][j][2], c[i][j][3],
                                 a0[i], a1[i], a2[i], a3[i], blo[j], bhi[j]);
            }

            // ---- pass 1: d values + per-row tile minima -> smem running min ----
            float rmin_lo[4], rmin_hi[4];
#pragma unroll
            for (int i = 0; i < 4; i++) {
                const int rlo = wm * 64 + i * 16 + g;
                const float zlo = zzs[rlo];
                const float zhi = zzs[rlo + 8];
                float ml = __int_as_float(0x7f800000);
                float mh = __int_as_float(0x7f800000);
#pragma unroll
                for (int j = 0; j < 4; j++) {
                    const int col0 = wn * 32 + j * 8 + 2 * q;
                    const float e0 = ees[col0];
                    const float e1 = ees[col0 + 1];
                    c[i][j][0] = (zlo + e0) - 2.0f * c[i][j][0];
                    c[i][j][1] = (zlo + e1) - 2.0f * c[i][j][1];
                    c[i][j][2] = (zhi + e0) - 2.0f * c[i][j][2];
                    c[i][j][3] = (zhi + e1) - 2.0f * c[i][j][3];
                    ml = fminf(ml, fminf(c[i][j][0], c[i][j][1]));
                    mh = fminf(mh, fminf(c[i][j][2], c[i][j][3]));
                }
                rmin_lo[i] = ml;
                rmin_hi[i] = mh;
            }
#pragma unroll
            for (int o = 1; o < 4; o <<= 1) {
#pragma unroll
                for (int i = 0; i < 4; i++) {
                    rmin_lo[i] = fminf(rmin_lo[i], __shfl_xor_sync(0xffffffffu, rmin_lo[i], o));
                    rmin_hi[i] = fminf(rmin_hi[i], __shfl_xor_sync(0xffffffffu, rmin_hi[i], o));
                }
            }
            if (q == 0) {
#pragma unroll
                for (int i = 0; i < 4; i++) {
                    const int rlo = wm * 64 + i * 16 + g;
                    atomicMin(&bdU[rlo], __float_as_uint(rmin_lo[i]));
                    atomicMin(&bdU[rlo + 8], __float_as_uint(rmin_hi[i]));
                }
            }
            __syncthreads();

            // ---- pass 2: collect candidates with d <= bd + delta ----
#pragma unroll
            for (int i = 0; i < 4; i++) {
                const int rlo = wm * 64 + i * 16 + g;
                const float bl = __uint_as_float(bdU[rlo]) + DELTA;
                const float bh = __uint_as_float(bdU[rlo + 8]) + DELTA;
                const int growlo = row0 + rlo;
                const int growhi = growlo + 8;
#pragma unroll
                for (int j = 0; j < 4; j++) {
                    const int col0 = t * 128 + wn * 32 + j * 8 + 2 * q;
                    if (c[i][j][0] <= bl) {
                        int sl = atomicAdd(&g_ncand[growlo], 1);
                        if (sl < CAP) g_cand[growlo * CAP + sl] = col0;
                    }
                    if (c[i][j][1] <= bl) {
                        int sl = atomicAdd(&g_ncand[growlo], 1);
                        if (sl < CAP) g_cand[growlo * CAP + sl] = col0 + 1;
                    }
                    if (c[i][j][2] <= bh) {
                        int sl = atomicAdd(&g_ncand[growhi], 1);
                        if (sl < CAP) g_cand[growhi * CAP + sl] = col0;
                    }
                    if (c[i][j][3] <= bh) {
                        int sl = atomicAdd(&g_ncand[growhi], 1);
                        if (sl < CAP) g_cand[growhi * CAP + sl] = col0 + 1;
                    }
                }
            }
            __syncthreads();   // pass2 done before next tile's ees/B overwrite
        }
    }
}

// -------- exact rescore of candidates (identical math to R1/R2 exact path) --------
__global__ void __launch_bounds__(256) vq_rescore_kernel(const float* __restrict__ z,
                                                         const float* __restrict__ cb) {
    __shared__ float zs[8][DD];
    const int tid = threadIdx.x;
    const int wid = tid >> 5, lid = tid & 31;
    const int row = blockIdx.x * 8 + wid;

    const float4* zr = reinterpret_cast<const float4*>(z + (size_t)row * DD);
    float4* zd = reinterpret_cast<float4*>(zs[wid]);
#pragma unroll
    for (int i = 0; i < 2; i++) zd[lid + 32 * i] = zr[lid + 32 * i];
    __syncwarp();

    const float zz = g_zz[row];
    const int nc = g_ncand[row];
    const bool full = (nc > CAP);           // overflow -> exact full scan
    const int n = full ? KCODES : nc;

    float bd = __int_as_float(0x7f800000);
    int bk = 0x7fffffff;
    for (int i = lid; i < n; i += 32) {
        const int code = full ? i : g_cand[row * CAP + i];
        const float4* e = reinterpret_cast<const float4*>(cb + (size_t)code * DD);
        float s = 0.f;
#pragma unroll
        for (int k4 = 0; k4 < DD / 4; k4++) {
            float4 ev = e[k4];
            float4 zv = zd[k4];
            s = fmaf(zv.x, ev.x, s); s = fmaf(zv.y, ev.y, s);
            s = fmaf(zv.z, ev.z, s); s = fmaf(zv.w, ev.w, s);
        }
        const float d = (zz + g_ee[code]) - 2.0f * s;
        if (d < bd || (d == bd && code < bk)) { bd = d; bk = code; }
    }
#pragma unroll
    for (int o = 16; o; o >>= 1) {
        float od = __shfl_xor_sync(0xffffffffu, bd, o);
        int ok = __shfl_xor_sync(0xffffffffu, bk, o);
        if (od < bd || (od == bd && ok < bk)) { bd = od; bk = ok; }
    }
    if (lid == 0) g_bestk[row] = bk;
}

// -------- output gather + straight-through + loss partials --------
__global__ void vq_output_kernel(const float* __restrict__ z, const float* __restrict__ cb,
                                 float* __restrict__ out) {
    const int tid = threadIdx.x;
    const size_t g4 = (size_t)blockIdx.x * 256 + tid;
    const int row = (int)(g4 >> 6);
    const int c4 = (int)(g4 & 63);
    const int idx = g_bestk[row];

    const float4 zv = reinterpret_cast<const float4*>(z)[g4];
    const float4 qv = reinterpret_cast<const float4*>(cb)[(size_t)idx * 64 + c4];

    float4 o;
    o.x = zv.x + (qv.x - zv.x);
    o.y = zv.y + (qv.y - zv.y);
    o.z = zv.z + (qv.z - zv.z);
    o.w = zv.w + (qv.w - zv.w);
    reinterpret_cast<float4*>(out)[g4] = o;

    const float dx = zv.x - qv.x, dy = zv.y - qv.y, dz = zv.z - qv.z, dw = zv.w - qv.w;
    float part = dx * dx;
    part = fmaf(dy, dy, part);
    part = fmaf(dz, dz, part);
    part = fmaf(dw, dw, part);

    __shared__ float sp[256];
    sp[tid] = part;
    __syncthreads();
#pragma unroll
    for (int s = 128; s; s >>= 1) {
        if (tid < s) sp[tid] += sp[tid + s];
        __syncthreads();
    }
    if (tid == 0) g_partial[blockIdx.x] = sp[0];
}

// -------- deterministic final loss reduction --------
__global__ void vq_loss_kernel(float* __restrict__ out, int out_size) {
    __shared__ double sm[256];
    const int tid = threadIdx.x;
    double s = 0.0;
    for (int i = tid; i < 8192; i += 256) s += (double)g_partial[i];
    sm[tid] = s;
    __syncthreads();
#pragma unroll
    for (int st = 128; st; st >>= 1) {
        if (tid < st) sm[tid] += sm[tid + st];
        __syncthreads();
    }
    if (tid == 0) {
        const float m = (float)(sm[0] / (double)QSIZE);
        const float vq = 0.25f * m + m;
        for (int i = QSIZE; i < out_size; i++) out[i] = vq;
    }
}

extern "C" void kernel_launch(void* const* d_in, const int* in_sizes, int n_in,
                              void* d_out, int out_size) {
    const float* z  = (const float*)d_in[0];
    const float* cb = (const float*)d_in[1];
    if (n_in >= 2 && in_sizes[0] == KCODES * DD && in_sizes[1] == NROWS * DD) {
        const float* t = z; z = cb; cb = t;
    }
    float* out = (float*)d_out;

    cudaFuncSetAttribute(vq_screen_kernel,
                         cudaFuncAttributeMaxDynamicSharedMemorySize, SM_TOTAL);

    float* zz_ptr; cudaGetSymbolAddress((void**)&zz_ptr, g_zz);
    float* ee_ptr; cudaGetSymbolAddress((void**)&ee_ptr, g_ee);

    vq_init_kernel<<<NROWS / 256, 256>>>();
    vq_norms_kernel<<<(NROWS * 32) / 256, 256>>>(z, zz_ptr, NROWS);
    vq_norms_kernel<<<(KCODES * 32) / 256, 256>>>(cb, ee_ptr, KCODES);
    vq_cvt_kernel<<<(KCODES * DD / 4) / 256, 256>>>(cb);
    vq_screen_kernel<<<148, 256, SM_TOTAL>>>(z);
    vq_rescore_kernel<<<NROWS / 8, 256>>>(z, cb);
    vq_output_kernel<<<QSIZE / 1024, 256>>>(z, cb, out);
    vq_loss_kernel<<<1, 256>>>(out, out_size);
}